// round 5
// baseline (speedup 1.0000x reference)
#include <cuda_runtime.h>
#include <math.h>

#define SEQ   512
#define BAT   32
#define DIM   768
#define NH    12
#define DH    64
#define GT    16
#define NCTX  8
#define RB    4
#define NKG   4112   /* GT + NCTX*SEQ */
#define SCALE 0.125f /* 1/sqrt(64) */

// ---------------- scratch (static device globals; no allocation) ----------------
__device__ float g_q [BAT*SEQ*DIM];
__device__ float g_k [BAT*SEQ*DIM];
__device__ float g_v [BAT*SEQ*DIM];
__device__ float g_gq[RB*GT*DIM];
__device__ float g_gk[RB*GT*DIM];
__device__ float g_gv[RB*GT*DIM];
__device__ float g_gs[RB*NH*GT*NKG];

// ============================================================================
// QKV projection GEMM: C = A[M,768] @ W[768,768] + bias.
// blockIdx.z selects (Wq,bq,outq) / (Wk,...) / (Wv,...).
// 128x128 tile, BK=8, 256 threads, 8x8 per-thread microtile.
// ============================================================================
__global__ __launch_bounds__(256)
void qkv_gemm(const float* __restrict__ A, int M,
              const float* __restrict__ Wq, const float* __restrict__ Wk,
              const float* __restrict__ Wv,
              const float* __restrict__ bq, const float* __restrict__ bk,
              const float* __restrict__ bv,
              float* __restrict__ outq, float* __restrict__ outk,
              float* __restrict__ outv)
{
    const int z = blockIdx.z;
    const float* __restrict__ W    = (z == 0) ? Wq : (z == 1) ? Wk : Wv;
    const float* __restrict__ bias = (z == 0) ? bq : (z == 1) ? bk : bv;
    float* __restrict__ C          = (z == 0) ? outq : (z == 1) ? outk : outv;

    __shared__ float As[8][128];
    __shared__ float Bs[8][128];

    const int tid = threadIdx.x;
    const int m0 = blockIdx.y * 128;
    const int n0 = blockIdx.x * 128;

    const int tx = tid & 15;   // 0..15 -> 8 N-cols each
    const int ty = tid >> 4;   // 0..15 -> 8 M-rows each

    const int arow = tid >> 1;        // 0..127
    const int acol = (tid & 1) * 4;   // 0 or 4
    const int brow = tid >> 5;        // 0..7
    const int bcol = (tid & 31) * 4;  // 0..124

    float acc[8][8];
#pragma unroll
    for (int i = 0; i < 8; i++)
#pragma unroll
        for (int j = 0; j < 8; j++) acc[i][j] = 0.f;

    for (int k0 = 0; k0 < DIM; k0 += 8) {
        // load A tile (transposed into As[k][m]); guard rows for M=64 case
        float4 av = make_float4(0.f, 0.f, 0.f, 0.f);
        if (m0 + arow < M)
            av = *(const float4*)&A[(size_t)(m0 + arow) * DIM + k0 + acol];
        As[acol + 0][arow] = av.x;
        As[acol + 1][arow] = av.y;
        As[acol + 2][arow] = av.z;
        As[acol + 3][arow] = av.w;
        // load W tile
        *(float4*)&Bs[brow][bcol] =
            *(const float4*)&W[(size_t)(k0 + brow) * DIM + n0 + bcol];
        __syncthreads();

#pragma unroll
        for (int kk = 0; kk < 8; kk++) {
            float4 a0 = *(const float4*)&As[kk][ty * 8];
            float4 a1 = *(const float4*)&As[kk][ty * 8 + 4];
            float4 b0 = *(const float4*)&Bs[kk][tx * 8];
            float4 b1 = *(const float4*)&Bs[kk][tx * 8 + 4];
            float a[8] = {a0.x, a0.y, a0.z, a0.w, a1.x, a1.y, a1.z, a1.w};
            float b[8] = {b0.x, b0.y, b0.z, b0.w, b1.x, b1.y, b1.z, b1.w};
#pragma unroll
            for (int i = 0; i < 8; i++)
#pragma unroll
                for (int j = 0; j < 8; j++) acc[i][j] = fmaf(a[i], b[j], acc[i][j]);
        }
        __syncthreads();
    }

#pragma unroll
    for (int i = 0; i < 8; i++) {
        int m = m0 + ty * 8 + i;
        if (m < M) {
#pragma unroll
            for (int jq = 0; jq < 2; jq++) {
                int n = n0 + tx * 8 + jq * 4;
                float4 bv4 = *(const float4*)&bias[n];
                float4 cv;
                cv.x = acc[i][jq * 4 + 0] + bv4.x;
                cv.y = acc[i][jq * 4 + 1] + bv4.y;
                cv.z = acc[i][jq * 4 + 2] + bv4.z;
                cv.w = acc[i][jq * 4 + 3] + bv4.w;
                *(float4*)&C[(size_t)m * DIM + n] = cv;
            }
        }
    }
}

// ============================================================================
// Local attention: each context attends to [16 global tokens ; its own 512].
// Grid (4, 12, 32) = (s_blk, h, b); 128 threads; thread = one query row.
// Online softmax over 33 key-tiles of 16 (tile 0 = the 16 global keys).
// ============================================================================
__global__ __launch_bounds__(128)
void local_attn(const float* __restrict__ Q, const float* __restrict__ K,
                const float* __restrict__ V, const float* __restrict__ GK,
                const float* __restrict__ GV, const float* __restrict__ mask,
                float* __restrict__ out)
{
    const int sblk = blockIdx.x, h = blockIdx.y, b = blockIdx.z;
    const int rb = b >> 3;
    const int tid = threadIdx.x;
    const int s = sblk * 128 + tid;

    __shared__ float4 Ks[16][16];
    __shared__ float4 Vs[16][16];
    __shared__ float  mk[16];

    float4 q[16];
    {
        const float4* qp = (const float4*)&Q[((size_t)b * SEQ + s) * DIM + h * DH];
#pragma unroll
        for (int i = 0; i < 16; i++) q[i] = qp[i];
    }

    float4 acc[16];
#pragma unroll
    for (int i = 0; i < 16; i++) acc[i] = make_float4(0.f, 0.f, 0.f, 0.f);
    float mrun = -1e30f, lrun = 0.f;

    for (int t = 0; t < 33; t++) {
        const int jj0 = t * 16;
        __syncthreads();
#pragma unroll
        for (int i = 0; i < 2; i++) {
            int idx = i * 128 + tid;          // 0..255
            int row = idx >> 4, d4 = idx & 15;
            int jj = jj0 + row;
            const float *kp, *vp;
            if (jj < GT) {
                kp = GK + ((size_t)rb * GT + jj) * DIM + h * DH;
                vp = GV + ((size_t)rb * GT + jj) * DIM + h * DH;
            } else {
                size_t off = ((size_t)b * SEQ + (jj - GT)) * DIM + h * DH;
                kp = K + off;
                vp = V + off;
            }
            Ks[row][d4] = ((const float4*)kp)[d4];
            Vs[row][d4] = ((const float4*)vp)[d4];
        }
        if (tid < 16) {
            int jj = jj0 + tid;
            mk[tid] = (jj < GT) ? 0.f : mask[(size_t)b * SEQ + jj - GT];
        }
        __syncthreads();

        float sc[16];
#pragma unroll
        for (int j = 0; j < 16; j++) {
            float sj = 0.f;
#pragma unroll
            for (int d = 0; d < 16; d++) {
                float4 kv = Ks[j][d];
                sj = fmaf(q[d].x, kv.x, sj);
                sj = fmaf(q[d].y, kv.y, sj);
                sj = fmaf(q[d].z, kv.z, sj);
                sj = fmaf(q[d].w, kv.w, sj);
            }
            sc[j] = sj * SCALE + mk[j];
        }
        float tm = sc[0];
#pragma unroll
        for (int j = 1; j < 16; j++) tm = fmaxf(tm, sc[j]);
        float mnew = fmaxf(mrun, tm);
        float f = __expf(mrun - mnew);
        lrun *= f;
#pragma unroll
        for (int i = 0; i < 16; i++) {
            acc[i].x *= f; acc[i].y *= f; acc[i].z *= f; acc[i].w *= f;
        }
#pragma unroll
        for (int j = 0; j < 16; j++) {
            float p = __expf(sc[j] - mnew);
            lrun += p;
#pragma unroll
            for (int d = 0; d < 16; d++) {
                float4 vv = Vs[j][d];
                acc[d].x = fmaf(p, vv.x, acc[d].x);
                acc[d].y = fmaf(p, vv.y, acc[d].y);
                acc[d].z = fmaf(p, vv.z, acc[d].z);
                acc[d].w = fmaf(p, vv.w, acc[d].w);
            }
        }
        mrun = mnew;
    }

    const float inv = 1.f / lrun;
    float4* op = (float4*)&out[((size_t)b * SEQ + s) * DIM + h * DH];
#pragma unroll
    for (int i = 0; i < 16; i++) {
        float4 o = acc[i];
        o.x *= inv; o.y *= inv; o.z *= inv; o.w *= inv;
        op[i] = o;
    }
}

// ============================================================================
// Global attention, pass 1: scores = gq @ full_k^T * scale + mask.
// Grid (33, 12, 4) = (key_tile_of_128, h, rb); 256 threads.
// ============================================================================
__global__ __launch_bounds__(256)
void g_scores_kernel(const float* __restrict__ GQ, const float* __restrict__ K,
                     const float* __restrict__ GK, const float* __restrict__ mask,
                     float* __restrict__ sc)
{
    const int kt = blockIdx.x, h = blockIdx.y, rb = blockIdx.z;
    const int t = threadIdx.x;

    __shared__ float  qs[16][68];     // padded: 2-way conflicts max
    __shared__ float4 Ks[128][16];

    {   // load 16 query rows
        int g = t >> 4, d4 = t & 15;
        float4 v = *(const float4*)&GQ[((size_t)rb * GT + g) * DIM + h * DH + d4 * 4];
        *(float4*)&qs[g][d4 * 4] = v;
    }
#pragma unroll
    for (int i = 0; i < 8; i++) {   // load 128 key rows
        int idx = i * 256 + t;
        int row = idx >> 4, d4 = idx & 15;
        int jj = kt * 128 + row;
        float4 val = make_float4(0.f, 0.f, 0.f, 0.f);
        if (jj < NKG) {
            const float* ptr;
            if (jj < GT) ptr = GK + ((size_t)rb * GT + jj) * DIM + h * DH;
            else {
                int tt = jj - GT;
                ptr = K + (((size_t)rb * NCTX + (tt >> 9)) * SEQ + (tt & 511)) * DIM + h * DH;
            }
            val = ((const float4*)ptr)[d4];
        }
        Ks[row][d4] = val;
    }
    __syncthreads();

    const int g  = t & 15;
    const int j0 = t >> 4;
#pragma unroll
    for (int jp = 0; jp < 8; jp++) {
        int j = jp * 16 + j0;
        float s = 0.f;
#pragma unroll
        for (int d = 0; d < 16; d++) {
            float4 kv = Ks[j][d];
            float4 qv = *(const float4*)&qs[g][d * 4];
            s = fmaf(qv.x, kv.x, s);
            s = fmaf(qv.y, kv.y, s);
            s = fmaf(qv.z, kv.z, s);
            s = fmaf(qv.w, kv.w, s);
        }
        int jj = kt * 128 + j;
        if (jj < NKG) {
            float gm = (jj < GT) ? 0.f : mask[(size_t)rb * (NCTX * SEQ) + jj - GT];
            sc[(((size_t)rb * NH + h) * GT + g) * NKG + jj] = s * SCALE + gm;
        }
    }
}

// ============================================================================
// Global attention, pass 2: row softmax in place. Grid 768 rows, 256 threads.
// ============================================================================
__global__ __launch_bounds__(256)
void g_softmax_kernel(float* __restrict__ sc)
{
    __shared__ float red[256];
    const int row = blockIdx.x, t = threadIdx.x;
    float* p = sc + (size_t)row * NKG;

    float mx = -1e30f;
    for (int i = t; i < NKG; i += 256) mx = fmaxf(mx, p[i]);
    red[t] = mx;
    __syncthreads();
    for (int off = 128; off > 0; off >>= 1) {
        if (t < off) red[t] = fmaxf(red[t], red[t + off]);
        __syncthreads();
    }
    mx = red[0];
    __syncthreads();

    float sum = 0.f;
    for (int i = t; i < NKG; i += 256) {
        float e = __expf(p[i] - mx);
        p[i] = e;
        sum += e;
    }
    red[t] = sum;
    __syncthreads();
    for (int off = 128; off > 0; off >>= 1) {
        if (t < off) red[t] += red[t + off];
        __syncthreads();
    }
    float inv = 1.f / red[0];
    for (int i = t; i < NKG; i += 256) p[i] *= inv;
}

// ============================================================================
// Global attention, pass 3: g_ctx = probs @ full_v. Grid (12, 4) = (h, rb).
// 256 threads; thread owns (g = t/16, 4 output dims at (t%16)*4).
// ============================================================================
__global__ __launch_bounds__(256)
void g_ctx_kernel(const float* __restrict__ P, const float* __restrict__ V,
                  const float* __restrict__ GV, float* __restrict__ gout)
{
    const int h = blockIdx.x, rb = blockIdx.y;
    const int t = threadIdx.x;

    __shared__ float4 Vs[64][16];
    __shared__ float  ps[16][64];

    const int g = t >> 4;
    const int dq = t & 15;
    float4 acc = make_float4(0.f, 0.f, 0.f, 0.f);

    for (int kt = 0; kt < 65; kt++) {
        const int jj0 = kt * 64;
        __syncthreads();
#pragma unroll
        for (int i = 0; i < 4; i++) {
            int idx = i * 256 + t;
            int row = idx >> 4, d4 = idx & 15;
            int jj = jj0 + row;
            float4 val = make_float4(0.f, 0.f, 0.f, 0.f);
            if (jj < NKG) {
                const float* ptr;
                if (jj < GT) ptr = GV + ((size_t)rb * GT + jj) * DIM + h * DH;
                else {
                    int tt = jj - GT;
                    ptr = V + (((size_t)rb * NCTX + (tt >> 9)) * SEQ + (tt & 511)) * DIM + h * DH;
                }
                val = ((const float4*)ptr)[d4];
            }
            Vs[row][d4] = val;
        }
#pragma unroll
        for (int i = 0; i < 4; i++) {
            int idx = i * 256 + t;
            int pg = idx >> 6, j = idx & 63;
            int jj = jj0 + j;
            ps[pg][j] = (jj < NKG)
                ? P[(((size_t)rb * NH + h) * GT + pg) * NKG + jj] : 0.f;
        }
        __syncthreads();
#pragma unroll
        for (int j = 0; j < 64; j++) {
            float p = ps[g][j];
            float4 vv = Vs[j][dq];
            acc.x = fmaf(p, vv.x, acc.x);
            acc.y = fmaf(p, vv.y, acc.y);
            acc.z = fmaf(p, vv.z, acc.z);
            acc.w = fmaf(p, vv.w, acc.w);
        }
    }
    *(float4*)&gout[((size_t)rb * GT + g) * DIM + h * DH + dq * 4] = acc;
}

// ============================================================================
extern "C" void kernel_launch(void* const* d_in, const int* in_sizes, int n_in,
                              void* d_out, int out_size)
{
    const float* hs   = (const float*)d_in[0];   // hidden_states  [32,512,768]
    const float* mask = (const float*)d_in[1];   // attention_mask [32,1,1,512]
    const float* gte  = (const float*)d_in[2];   // global_tokens  [4,16,768]
    const float* Wq   = (const float*)d_in[3];
    const float* bq   = (const float*)d_in[4];
    const float* Wk   = (const float*)d_in[5];
    const float* bk   = (const float*)d_in[6];
    const float* Wv   = (const float*)d_in[7];
    const float* bv   = (const float*)d_in[8];
    float* out = (float*)d_out;                  // ctx [32,512,768] ; g_ctx [4,16,768]

    float *q, *k, *v, *gq, *gk, *gv, *gs;
    cudaGetSymbolAddress((void**)&q,  g_q);
    cudaGetSymbolAddress((void**)&k,  g_k);
    cudaGetSymbolAddress((void**)&v,  g_v);
    cudaGetSymbolAddress((void**)&gq, g_gq);
    cudaGetSymbolAddress((void**)&gk, g_gk);
    cudaGetSymbolAddress((void**)&gv, g_gv);
    cudaGetSymbolAddress((void**)&gs, g_gs);

    // QKV projections: packed contexts (M=16384) and global tokens (M=64)
    qkv_gemm<<<dim3(6, 128, 3), 256>>>(hs, BAT * SEQ, Wq, Wk, Wv, bq, bk, bv, q, k, v);
    qkv_gemm<<<dim3(6, 1,   3), 256>>>(gte, RB * GT,  Wq, Wk, Wv, bq, bk, bv, gq, gk, gv);

    // Global-token cross attention
    g_scores_kernel<<<dim3(33, NH, RB), 256>>>(gq, k, gk, mask, gs);
    g_softmax_kernel<<<RB * NH * GT, 256>>>(gs);
    g_ctx_kernel<<<dim3(NH, RB), 256>>>(gs, v, gv, out + (size_t)BAT * SEQ * DIM);

    // Local attention
    local_attn<<<dim3(4, NH, BAT), 128>>>(q, k, v, gk, gv, mask, out);
}

// round 6
// speedup vs baseline: 1.0215x; 1.0215x over previous
#include <cuda_runtime.h>
#include <math.h>

#define SEQ   512
#define BAT   32
#define DIM   768
#define NH    12
#define DH    64
#define GT    16
#define NCTX  8
#define RB    4
#define NKG   4112   /* GT + NCTX*SEQ */
#define SCALE 0.125f /* 1/sqrt(64) */

typedef unsigned long long u64;

// ---- packed fp32x2 helpers (SASS FFMA2/FMUL2 — PTX-only path on sm_103a) ----
__device__ __forceinline__ u64 pk2(float x, float y) {
    u64 r; asm("mov.b64 %0, {%1, %2};" : "=l"(r) : "f"(x), "f"(y)); return r;
}
__device__ __forceinline__ float2 up2(u64 a) {
    float2 f; asm("mov.b64 {%0, %1}, %2;" : "=f"(f.x), "=f"(f.y) : "l"(a)); return f;
}
__device__ __forceinline__ void fma2(u64& d, u64 a, u64 b) {
    asm("fma.rn.f32x2 %0, %1, %2, %0;" : "+l"(d) : "l"(a), "l"(b));
}
__device__ __forceinline__ void mul2(u64& d, u64 a, u64 b) {
    asm("mul.rn.f32x2 %0, %1, %2;" : "=l"(d) : "l"(a), "l"(b));
}

// ---------------- scratch (static device globals; no allocation) ----------------
__device__ float g_q [BAT*SEQ*DIM];
__device__ float g_k [BAT*SEQ*DIM];
__device__ float g_v [BAT*SEQ*DIM];
__device__ float g_gq[RB*GT*DIM];
__device__ float g_gk[RB*GT*DIM];
__device__ float g_gv[RB*GT*DIM];
__device__ float g_gs[RB*NH*GT*NKG];

// ============================================================================
// QKV projection GEMM: C = A[M,768] @ W[768,768] + bias. f32x2 microkernel.
// 128x128 tile, BK=8, 256 threads, 8x8 per-thread microtile (packed 8x4 u64).
// ============================================================================
__global__ __launch_bounds__(256)
void qkv_gemm(const float* __restrict__ A, int M,
              const float* __restrict__ Wq, const float* __restrict__ Wk,
              const float* __restrict__ Wv,
              const float* __restrict__ bq, const float* __restrict__ bk,
              const float* __restrict__ bv,
              float* __restrict__ outq, float* __restrict__ outk,
              float* __restrict__ outv)
{
    const int z = blockIdx.z;
    const float* __restrict__ W    = (z == 0) ? Wq : (z == 1) ? Wk : Wv;
    const float* __restrict__ bias = (z == 0) ? bq : (z == 1) ? bk : bv;
    float* __restrict__ C          = (z == 0) ? outq : (z == 1) ? outk : outv;

    __shared__ float As[8][128];
    __shared__ float Bs[8][128];

    const int tid = threadIdx.x;
    const int m0 = blockIdx.y * 128;
    const int n0 = blockIdx.x * 128;

    const int tx = tid & 15;   // 8 N-cols each
    const int ty = tid >> 4;   // 8 M-rows each

    const int arow = tid >> 1;        // 0..127
    const int acol = (tid & 1) * 4;   // 0 or 4
    const int brow = tid >> 5;        // 0..7
    const int bcol = (tid & 31) * 4;  // 0..124

    u64 acc[8][4];
#pragma unroll
    for (int i = 0; i < 8; i++)
#pragma unroll
        for (int j = 0; j < 4; j++) acc[i][j] = 0ULL;

    for (int k0 = 0; k0 < DIM; k0 += 8) {
        float4 av = make_float4(0.f, 0.f, 0.f, 0.f);
        if (m0 + arow < M)
            av = *(const float4*)&A[(size_t)(m0 + arow) * DIM + k0 + acol];
        As[acol + 0][arow] = av.x;
        As[acol + 1][arow] = av.y;
        As[acol + 2][arow] = av.z;
        As[acol + 3][arow] = av.w;
        *(float4*)&Bs[brow][bcol] =
            *(const float4*)&W[(size_t)(k0 + brow) * DIM + n0 + bcol];
        __syncthreads();

#pragma unroll
        for (int kk = 0; kk < 8; kk++) {
            float4 a0 = *(const float4*)&As[kk][ty * 8];
            float4 a1 = *(const float4*)&As[kk][ty * 8 + 4];
            // b pairs come directly as 64-bit lanes from two LDS.128s
            ulonglong2 bA = *(const ulonglong2*)&Bs[kk][tx * 8];
            ulonglong2 bB = *(const ulonglong2*)&Bs[kk][tx * 8 + 4];
            float a[8] = {a0.x, a0.y, a0.z, a0.w, a1.x, a1.y, a1.z, a1.w};
#pragma unroll
            for (int i = 0; i < 8; i++) {
                u64 aa = pk2(a[i], a[i]);
                fma2(acc[i][0], aa, bA.x);
                fma2(acc[i][1], aa, bA.y);
                fma2(acc[i][2], aa, bB.x);
                fma2(acc[i][3], aa, bB.y);
            }
        }
        __syncthreads();
    }

#pragma unroll
    for (int i = 0; i < 8; i++) {
        int m = m0 + ty * 8 + i;
        if (m < M) {
#pragma unroll
            for (int jq = 0; jq < 2; jq++) {
                int n = n0 + tx * 8 + jq * 4;
                float4 bv4 = *(const float4*)&bias[n];
                float2 c0 = up2(acc[i][jq * 2 + 0]);
                float2 c1 = up2(acc[i][jq * 2 + 1]);
                float4 cv;
                cv.x = c0.x + bv4.x;
                cv.y = c0.y + bv4.y;
                cv.z = c1.x + bv4.z;
                cv.w = c1.y + bv4.w;
                *(float4*)&C[(size_t)m * DIM + n] = cv;
            }
        }
    }
}

// ============================================================================
// Local attention: each context attends to [16 global tokens ; its own 512].
// Grid (4, 12, 32); 128 threads; thread = one query row; f32x2 inner loops.
// ============================================================================
__global__ __launch_bounds__(128)
void local_attn(const float* __restrict__ Q, const float* __restrict__ K,
                const float* __restrict__ V, const float* __restrict__ GK,
                const float* __restrict__ GV, const float* __restrict__ mask,
                float* __restrict__ out)
{
    const int sblk = blockIdx.x, h = blockIdx.y, b = blockIdx.z;
    const int rb = b >> 3;
    const int tid = threadIdx.x;
    const int s = sblk * 128 + tid;

    __shared__ float4 Ks[16][16];
    __shared__ float4 Vs[16][16];
    __shared__ float  mk[16];

    ulonglong2 q[16];    // 64 packed fp32 pairs
    {
        const ulonglong2* qp =
            (const ulonglong2*)&Q[((size_t)b * SEQ + s) * DIM + h * DH];
#pragma unroll
        for (int i = 0; i < 16; i++) q[i] = qp[i];
    }

    u64 acc[32];
#pragma unroll
    for (int i = 0; i < 32; i++) acc[i] = 0ULL;
    float mrun = -1e30f, lrun = 0.f;

    for (int t = 0; t < 33; t++) {
        const int jj0 = t * 16;
        __syncthreads();
#pragma unroll
        for (int i = 0; i < 2; i++) {
            int idx = i * 128 + tid;
            int row = idx >> 4, d4 = idx & 15;
            int jj = jj0 + row;
            const float *kp, *vp;
            if (jj < GT) {
                kp = GK + ((size_t)rb * GT + jj) * DIM + h * DH;
                vp = GV + ((size_t)rb * GT + jj) * DIM + h * DH;
            } else {
                size_t off = ((size_t)b * SEQ + (jj - GT)) * DIM + h * DH;
                kp = K + off;
                vp = V + off;
            }
            Ks[row][d4] = ((const float4*)kp)[d4];
            Vs[row][d4] = ((const float4*)vp)[d4];
        }
        if (tid < 16) {
            int jj = jj0 + tid;
            mk[tid] = (jj < GT) ? 0.f : mask[(size_t)b * SEQ + jj - GT];
        }
        __syncthreads();

        float sc[16];
#pragma unroll
        for (int j = 0; j < 16; j++) {
            const ulonglong2* kr = (const ulonglong2*)Ks[j];
            u64 s0 = 0ULL, s1 = 0ULL;
#pragma unroll
            for (int d = 0; d < 16; d++) {
                ulonglong2 kv = kr[d];
                fma2(s0, q[d].x, kv.x);
                fma2(s1, q[d].y, kv.y);
            }
            float2 fa = up2(s0), fb = up2(s1);
            sc[j] = (fa.x + fa.y + fb.x + fb.y) * SCALE + mk[j];
        }
        float tm = sc[0];
#pragma unroll
        for (int j = 1; j < 16; j++) tm = fmaxf(tm, sc[j]);
        float mnew = fmaxf(mrun, tm);
        float f = __expf(mrun - mnew);
        lrun *= f;
        u64 ff = pk2(f, f);
#pragma unroll
        for (int i = 0; i < 32; i++) mul2(acc[i], acc[i], ff);
#pragma unroll
        for (int j = 0; j < 16; j++) {
            float p = __expf(sc[j] - mnew);
            lrun += p;
            u64 pp = pk2(p, p);
            const ulonglong2* vr = (const ulonglong2*)Vs[j];
#pragma unroll
            for (int d = 0; d < 16; d++) {
                ulonglong2 vv = vr[d];
                fma2(acc[2 * d + 0], pp, vv.x);
                fma2(acc[2 * d + 1], pp, vv.y);
            }
        }
        mrun = mnew;
    }

    const float inv = 1.f / lrun;
    u64 iv = pk2(inv, inv);
    ulonglong2* op = (ulonglong2*)&out[((size_t)b * SEQ + s) * DIM + h * DH];
#pragma unroll
    for (int i = 0; i < 16; i++) {
        ulonglong2 o;
        mul2(o.x, acc[2 * i + 0], iv);
        mul2(o.y, acc[2 * i + 1], iv);
        op[i] = o;
    }
}

// ============================================================================
// Global attention, pass 1: scores = gq @ full_k^T * scale + mask.
// Grid (33, 12, 4); 256 threads; f32x2.
// ============================================================================
__global__ __launch_bounds__(256)
void g_scores_kernel(const float* __restrict__ GQ, const float* __restrict__ K,
                     const float* __restrict__ GK, const float* __restrict__ mask,
                     float* __restrict__ sc)
{
    const int kt = blockIdx.x, h = blockIdx.y, rb = blockIdx.z;
    const int t = threadIdx.x;

    __shared__ float  qs[16][68];     // 68-stride keeps 16B alignment (272B rows)
    __shared__ float4 Ks[128][16];

    {
        int g = t >> 4, d4 = t & 15;
        float4 v = *(const float4*)&GQ[((size_t)rb * GT + g) * DIM + h * DH + d4 * 4];
        *(float4*)&qs[g][d4 * 4] = v;
    }
#pragma unroll
    for (int i = 0; i < 8; i++) {
        int idx = i * 256 + t;
        int row = idx >> 4, d4 = idx & 15;
        int jj = kt * 128 + row;
        float4 val = make_float4(0.f, 0.f, 0.f, 0.f);
        if (jj < NKG) {
            const float* ptr;
            if (jj < GT) ptr = GK + ((size_t)rb * GT + jj) * DIM + h * DH;
            else {
                int tt = jj - GT;
                ptr = K + (((size_t)rb * NCTX + (tt >> 9)) * SEQ + (tt & 511)) * DIM + h * DH;
            }
            val = ((const float4*)ptr)[d4];
        }
        Ks[row][d4] = val;
    }
    __syncthreads();

    const int g  = t & 15;
    const int j0 = t >> 4;
#pragma unroll
    for (int jp = 0; jp < 8; jp++) {
        int j = jp * 16 + j0;
        const ulonglong2* kr = (const ulonglong2*)Ks[j];
        u64 s0 = 0ULL, s1 = 0ULL;
#pragma unroll
        for (int d = 0; d < 16; d++) {
            ulonglong2 kv = kr[d];
            ulonglong2 qv = *(const ulonglong2*)&qs[g][d * 4];
            fma2(s0, qv.x, kv.x);
            fma2(s1, qv.y, kv.y);
        }
        float2 fa = up2(s0), fb = up2(s1);
        float sv = fa.x + fa.y + fb.x + fb.y;
        int jj = kt * 128 + j;
        if (jj < NKG) {
            float gm = (jj < GT) ? 0.f : mask[(size_t)rb * (NCTX * SEQ) + jj - GT];
            sc[(((size_t)rb * NH + h) * GT + g) * NKG + jj] = sv * SCALE + gm;
        }
    }
}

// ============================================================================
// Global attention, pass 2: row softmax in place. Grid 768 rows, 256 threads.
// ============================================================================
__global__ __launch_bounds__(256)
void g_softmax_kernel(float* __restrict__ sc)
{
    __shared__ float red[256];
    const int row = blockIdx.x, t = threadIdx.x;
    float* p = sc + (size_t)row * NKG;

    float mx = -1e30f;
    for (int i = t; i < NKG; i += 256) mx = fmaxf(mx, p[i]);
    red[t] = mx;
    __syncthreads();
    for (int off = 128; off > 0; off >>= 1) {
        if (t < off) red[t] = fmaxf(red[t], red[t + off]);
        __syncthreads();
    }
    mx = red[0];
    __syncthreads();

    float sum = 0.f;
    for (int i = t; i < NKG; i += 256) {
        float e = __expf(p[i] - mx);
        p[i] = e;
        sum += e;
    }
    red[t] = sum;
    __syncthreads();
    for (int off = 128; off > 0; off >>= 1) {
        if (t < off) red[t] += red[t + off];
        __syncthreads();
    }
    float inv = 1.f / red[0];
    for (int i = t; i < NKG; i += 256) p[i] *= inv;
}

// ============================================================================
// Global attention, pass 3: g_ctx = probs @ full_v. Grid (12, 4); f32x2.
// ============================================================================
__global__ __launch_bounds__(256)
void g_ctx_kernel(const float* __restrict__ P, const float* __restrict__ V,
                  const float* __restrict__ GV, float* __restrict__ gout)
{
    const int h = blockIdx.x, rb = blockIdx.y;
    const int t = threadIdx.x;

    __shared__ float4 Vs[64][16];
    __shared__ float  ps[16][64];

    const int g = t >> 4;
    const int dq = t & 15;
    u64 acc0 = 0ULL, acc1 = 0ULL;

    for (int kt = 0; kt < 65; kt++) {
        const int jj0 = kt * 64;
        __syncthreads();
#pragma unroll
        for (int i = 0; i < 4; i++) {
            int idx = i * 256 + t;
            int row = idx >> 4, d4 = idx & 15;
            int jj = jj0 + row;
            float4 val = make_float4(0.f, 0.f, 0.f, 0.f);
            if (jj < NKG) {
                const float* ptr;
                if (jj < GT) ptr = GV + ((size_t)rb * GT + jj) * DIM + h * DH;
                else {
                    int tt = jj - GT;
                    ptr = V + (((size_t)rb * NCTX + (tt >> 9)) * SEQ + (tt & 511)) * DIM + h * DH;
                }
                val = ((const float4*)ptr)[d4];
            }
            Vs[row][d4] = val;
        }
#pragma unroll
        for (int i = 0; i < 4; i++) {
            int idx = i * 256 + t;
            int pg = idx >> 6, j = idx & 63;
            int jj = jj0 + j;
            ps[pg][j] = (jj < NKG)
                ? P[(((size_t)rb * NH + h) * GT + pg) * NKG + jj] : 0.f;
        }
        __syncthreads();
#pragma unroll
        for (int j = 0; j < 64; j++) {
            u64 pp = pk2(ps[g][j], ps[g][j]);
            ulonglong2 vv = *(const ulonglong2*)&Vs[j][dq];
            fma2(acc0, pp, vv.x);
            fma2(acc1, pp, vv.y);
        }
    }
    ulonglong2 o; o.x = acc0; o.y = acc1;
    *(ulonglong2*)&gout[((size_t)rb * GT + g) * DIM + h * DH + dq * 4] = o;
}

// ============================================================================
extern "C" void kernel_launch(void* const* d_in, const int* in_sizes, int n_in,
                              void* d_out, int out_size)
{
    const float* hs   = (const float*)d_in[0];
    const float* mask = (const float*)d_in[1];
    const float* gte  = (const float*)d_in[2];
    const float* Wq   = (const float*)d_in[3];
    const float* bq   = (const float*)d_in[4];
    const float* Wk   = (const float*)d_in[5];
    const float* bk   = (const float*)d_in[6];
    const float* Wv   = (const float*)d_in[7];
    const float* bv   = (const float*)d_in[8];
    float* out = (float*)d_out;

    float *q, *k, *v, *gq, *gk, *gv, *gs;
    cudaGetSymbolAddress((void**)&q,  g_q);
    cudaGetSymbolAddress((void**)&k,  g_k);
    cudaGetSymbolAddress((void**)&v,  g_v);
    cudaGetSymbolAddress((void**)&gq, g_gq);
    cudaGetSymbolAddress((void**)&gk, g_gk);
    cudaGetSymbolAddress((void**)&gv, g_gv);
    cudaGetSymbolAddress((void**)&gs, g_gs);

    qkv_gemm<<<dim3(6, 128, 3), 256>>>(hs, BAT * SEQ, Wq, Wk, Wv, bq, bk, bv, q, k, v);
    qkv_gemm<<<dim3(6, 1,   3), 256>>>(gte, RB * GT,  Wq, Wk, Wv, bq, bk, bv, gq, gk, gv);

    g_scores_kernel<<<dim3(33, NH, RB), 256>>>(gq, k, gk, mask, gs);
    g_softmax_kernel<<<RB * NH * GT, 256>>>(gs);
    g_ctx_kernel<<<dim3(NH, RB), 256>>>(gs, v, gv, out + (size_t)BAT * SEQ * DIM);

    local_attn<<<dim3(4, NH, BAT), 128>>>(q, k, v, gk, gv, mask, out);
}